// round 9
// baseline (speedup 1.0000x reference)
#include <cuda_runtime.h>
#include <cuda_fp16.h>
#include <math.h>

// ---------------- problem constants ----------------
#define NC     32
#define NT     64
#define BATCHN 4096
#define NITEM  (BATCHN*NC)      // 131072 (b,c) items
#define P_TGT  1.0f
#define EPSB   1e-5f

// ---------------- MLP config ----------------
#define MLP_R   64                  // rows per CTA
#define AST     264                 // half-stride per activation row (528B, 16B-rotating)
#define SM_AL_OFF 16896             // AL base (half index) = 64*264
#define SM_XS_OFF 67584             // byte offset of staged inputs
#define MLP_SMEM (67584 + 2048)     // 69632 bytes

// bisection config
#define BGRD 512
#define BBLK 256

// ---------------- scratch (device globals; no allocation) ----------------
__device__ float4 d_FRF[BATCHN*NT];
__device__ float2 d_Hc [NITEM*4];
__device__ float  d_x  [NITEM*8];
__device__ float  d_mlp[NITEM*8];
__device__ float  d_poly[NITEM*8];
__device__ float  d_vp [NITEM*16];
__device__ float2 d_V  [NITEM*4];
__device__ float  d_P  [NITEM];
__device__ uint4  d_Wbp[32768];     // [L][s][n][kq] = {bh0,bh1,bl0,bl1}  512KB
__device__ float  d_part5[BGRD*31];
__device__ float  d_state[4];
__device__ int    d_it[1];
__device__ int    d_cnt;

// ---------------- helpers ----------------
__device__ __forceinline__ float2 cmul(float2 a, float2 b) {
    return make_float2(a.x*b.x - a.y*b.y, a.x*b.y + a.y*b.x);
}
__device__ __forceinline__ float2 cadd(float2 a, float2 b){ return make_float2(a.x+b.x, a.y+b.y); }
__device__ __forceinline__ float2 csub(float2 a, float2 b){ return make_float2(a.x-b.x, a.y-b.y); }
__device__ __forceinline__ float2 conj2(float2 a){ return make_float2(a.x, -a.y); }
__device__ __forceinline__ float wred(float v){
    #pragma unroll
    for (int o = 16; o; o >>= 1) v += __shfl_down_sync(0xffffffffu, v, o);
    return v;
}
__device__ __forceinline__ unsigned smem_u32(const void* p){
    unsigned a;
    asm("{ .reg .u64 t; cvta.to.shared.u64 t, %1; cvt.u32.u64 %0, t; }" : "=r"(a) : "l"(p));
    return a;
}
__device__ __forceinline__ unsigned pkh2(float lo, float hi){
    __half2 h = __floats2half2_rn(lo, hi);
    return *(unsigned*)&h;
}
__device__ __forceinline__ void ldm4(unsigned* r, unsigned addr){
    asm volatile("ldmatrix.sync.aligned.m8n8.x4.shared.b16 {%0,%1,%2,%3}, [%4];"
        : "=r"(r[0]), "=r"(r[1]), "=r"(r[2]), "=r"(r[3]) : "r"(addr));
}
__device__ __forceinline__ void mma16816(float* d, const unsigned* a, unsigned b0, unsigned b1){
    asm volatile("mma.sync.aligned.m16n8k16.row.col.f32.f16.f16.f32 "
        "{%0,%1,%2,%3}, {%4,%5,%6,%7}, {%8,%9}, {%0,%1,%2,%3};"
        : "+f"(d[0]), "+f"(d[1]), "+f"(d[2]), "+f"(d[3])
        : "r"(a[0]), "r"(a[1]), "r"(a[2]), "r"(a[3]), "r"(b0), "r"(b1));
}

// ---------------- K: fp16-split weight pack ----------------
// d_Wbp[((L*16+s)*256+n)*4+kq] = {h(k0,k0+1), h(k0+8,k0+9), l(k0,k0+1), l(k0+8,k0+9)}, k0=s*16+kq*2
__global__ void k_wpackh(const float* __restrict__ W1, const float* __restrict__ W2) {
    int idx = blockIdx.x * blockDim.x + threadIdx.x;   // 32768
    int kq = idx & 3, n = (idx >> 2) & 255, s = (idx >> 10) & 15, L = idx >> 14;
    const float* W = L ? W2 : W1;
    int k0 = s*16 + kq*2;
    float v[4];
    v[0] = W[(k0    )*256 + n];
    v[1] = W[(k0 + 1)*256 + n];
    v[2] = W[(k0 + 8)*256 + n];
    v[3] = W[(k0 + 9)*256 + n];
    float h[4], l[4];
    #pragma unroll
    for (int i = 0; i < 4; i++) {
        h[i] = __half2float(__float2half_rn(v[i]));
        l[i] = v[i] - h[i];
    }
    uint4 o;
    o.x = pkh2(h[0], h[1]);
    o.y = pkh2(h[2], h[3]);
    o.z = pkh2(l[0], l[1]);
    o.w = pkh2(l[2], l[3]);
    d_Wbp[idx] = o;
}

// ---------------- K1: F_RF ----------------
__global__ void k_frf(const float* __restrict__ H) {
    int warp = (blockIdx.x * blockDim.x + threadIdx.x) >> 5;
    int lane = threadIdx.x & 31;
    if (warp >= BATCHN) return;
    int b = warp;
    const float* r0 = H + ((b*2 + 0)*32 + 16)*128;
    const float* r1 = H + ((b*2 + 1)*32 + 16)*128;
    float im0 = r0[0];
    float im1 = r1[0];
    #pragma unroll
    for (int tt = 0; tt < 2; tt++) {
        int t = lane + tt*32;
        float re0 = r0[t], re1 = r1[t];
        float m0 = sqrtf(re0*re0 + im0*im0) * 8.0f;
        float m1 = sqrtf(re1*re1 + im1*im1) * 8.0f;
        float4 f;
        f.x =  re0 / m0;  f.y = -im0 / m0;
        f.z =  re1 / m1;  f.w = -im1 / m1;
        d_FRF[b*64 + t] = f;
    }
}

// ---------------- K2: H_equ (normalized) + features ----------------
__global__ void k_hequ(const float* __restrict__ H) {
    int warp = (blockIdx.x * blockDim.x + threadIdx.x) >> 5;
    int lane = threadIdx.x & 31;
    if (warp >= NITEM) return;
    int n = warp;
    int b = n >> 5, c = n & 31;
    int c3 = b >> 7;
    int b3 = ((b & 127) << 5) + c;

    float accr[2][2] = {{0,0},{0,0}};
    float acci[2][2] = {{0,0},{0,0}};
    #pragma unroll
    for (int i = 0; i < 2; i++) {
        int M  = c3*8192 + b3*2 + i;
        int bb = M >> 6, kk = (M >> 5) & 1, cc = M & 31;
        const float* row = H + ((bb*2 + kk)*32 + cc)*128;
        float him = row[0];
        #pragma unroll
        for (int tt = 0; tt < 2; tt++) {
            int t = lane + tt*32;
            float hre = row[t];
            float4 f = d_FRF[b3*64 + t];
            accr[i][0] += hre*f.x - him*f.y;
            acci[i][0] += hre*f.y + him*f.x;
            accr[i][1] += hre*f.z - him*f.w;
            acci[i][1] += hre*f.w + him*f.z;
        }
    }
    #pragma unroll
    for (int i = 0; i < 2; i++)
        #pragma unroll
        for (int k = 0; k < 2; k++) {
            accr[i][k] = wred(accr[i][k]);
            acci[i][k] = wred(acci[i][k]);
        }
    if (lane == 0) {
        float pw = 0.f;
        #pragma unroll
        for (int i = 0; i < 2; i++)
            #pragma unroll
            for (int k = 0; k < 2; k++)
                pw += accr[i][k]*accr[i][k] + acci[i][k]*acci[i][k];
        float inv = 1.0f / sqrtf(pw);
        #pragma unroll
        for (int i = 0; i < 2; i++)
            #pragma unroll
            for (int k = 0; k < 2; k++) {
                float re = accr[i][k]*inv, im = acci[i][k]*inv;
                d_Hc[n*4 + i*2 + k] = make_float2(re, im);
                d_x[n*8 + i*2 + k]     = re;
                d_x[n*8 + 4 + i*2 + k] = im;
            }
    }
}

// ---------------- K3: fused MLP, fp16-split m16n8k16, 16 warps/CTA ----------------
// Warp w: row block rb = w>>3 (32 rows), col block cb = w&7 (32 cols).
__global__ __launch_bounds__(512, 2)
void k_mlp(const float* __restrict__ W0, const float* __restrict__ b0,
           const float* __restrict__ b1, const float* __restrict__ b2,
           const float* __restrict__ W3, const float* __restrict__ b3) {
    extern __shared__ char smem[];
    __half* AH = (__half*)smem;
    __half* AL = AH + SM_AL_OFF;
    float*  XS = (float*)(smem + SM_XS_OFF);
    unsigned sbase = smem_u32(smem);
    int t = threadIdx.x;
    int w = t >> 5, lane = t & 31;
    int rb = w >> 3, cb = w & 7;
    int row0 = blockIdx.x * MLP_R;

    if (t < MLP_R*8) XS[t] = d_x[row0*8 + t];
    __syncthreads();

    // L0: 8 -> 256; thread = (column, row-half)
    {
        int c = t & 255, half = t >> 8;
        float wv[8];
        #pragma unroll
        for (int i = 0; i < 8; i++) wv[i] = W0[i*256 + c];
        float bs = __ldg(b0 + c);
        #pragma unroll 4
        for (int r = half*32; r < half*32 + 32; r++) {
            float acc = bs;
            #pragma unroll
            for (int i = 0; i < 8; i++) acc += XS[r*8 + i]*wv[i];
            acc = fmaxf(acc, 0.f);
            __half hh = __float2half_rn(acc);
            AH[r*AST + c] = hh;
            AL[r*AST + c] = __float2half_rn(acc - __half2float(hh));
        }
    }
    __syncthreads();

    for (int L = 0; L < 2; L++) {
        float acc[2][4][4];
        #pragma unroll
        for (int mt = 0; mt < 2; mt++)
            #pragma unroll
            for (int nt = 0; nt < 4; nt++)
                #pragma unroll
                for (int e = 0; e < 4; e++) acc[mt][nt][e] = 0.f;

        const uint4* WB = d_Wbp + (unsigned)(L*16)*1024;
        unsigned nbq = (unsigned)(cb*32 + (lane >> 2))*4 + (lane & 3);
        // ldmatrix base for this warp's 32-row block
        unsigned abase = sbase + (unsigned)(rb*32 + (lane & 15))*528 + ((unsigned)(lane >> 4) & 1)*16;

        #pragma unroll 2
        for (int s = 0; s < 16; s++) {
            uint4 bv[4];
            #pragma unroll
            for (int nt = 0; nt < 4; nt++) bv[nt] = WB[(unsigned)s*1024 + nbq + (unsigned)(nt*8)*4];

            #pragma unroll
            for (int mt = 0; mt < 2; mt++) {
                unsigned ah[4], al[4];
                unsigned ad = abase + (unsigned)(mt*16)*528 + (unsigned)s*32;
                ldm4(ah, ad);
                ldm4(al, ad + 33792);
                #pragma unroll
                for (int nt = 0; nt < 4; nt++) {
                    mma16816(acc[mt][nt], ah, bv[nt].x, bv[nt].y);
                    mma16816(acc[mt][nt], ah, bv[nt].z, bv[nt].w);
                    mma16816(acc[mt][nt], al, bv[nt].x, bv[nt].y);
                }
            }
        }
        __syncthreads();   // all reads of AH/AL complete

        if (L == 0) {
            // bias + relu + fp16 split -> back into AH/AL
            #pragma unroll
            for (int mt = 0; mt < 2; mt++)
                #pragma unroll
                for (int nt = 0; nt < 4; nt++) {
                    int r0 = rb*32 + mt*16 + (lane >> 2);
                    int c0 = cb*32 + nt*8 + 2*(lane & 3);
                    #pragma unroll
                    for (int e = 0; e < 4; e++) {
                        int r = r0 + (e >> 1)*8;
                        int c = c0 + (e & 1);
                        float x = fmaxf(acc[mt][nt][e] + __ldg(b1 + c), 0.f);
                        __half hh = __float2half_rn(x);
                        AH[r*AST + c] = hh;
                        AL[r*AST + c] = __float2half_rn(x - __half2float(hh));
                    }
                }
            __syncthreads();
        } else {
            // bias + relu -> float acts in smem (reuse AH/AL region), then L3
            float* AF = (float*)smem;   // stride 264 floats per row
            #pragma unroll
            for (int mt = 0; mt < 2; mt++)
                #pragma unroll
                for (int nt = 0; nt < 4; nt++) {
                    int r0 = rb*32 + mt*16 + (lane >> 2);
                    int c0 = cb*32 + nt*8 + 2*(lane & 3);
                    #pragma unroll
                    for (int e = 0; e < 4; e++) {
                        int r = r0 + (e >> 1)*8;
                        int c = c0 + (e & 1);
                        AF[r*264 + c] = fmaxf(acc[mt][nt][e] + __ldg(b2 + c), 0.f);
                    }
                }
            __syncthreads();

            // L3: 256 -> 8; one output per thread
            int r = t >> 3, p = t & 7;
            float a0 = __ldg(b3 + p);
            const float* rowf = AF + r*264;
            #pragma unroll 4
            for (int c = 0; c < 256; c++)
                a0 += rowf[c] * __ldg(W3 + c*8 + p);
            d_mlp[(row0 + r)*8 + p] = a0;
        }
    }
}

// ---------------- K0: bisection state init ----------------
__global__ void k_init(void) {
    d_state[0] = 0.0f; d_state[1] = 10.0f; d_state[2] = 0.0f; d_state[3] = 5.0f;
    d_it[0] = 0; d_cnt = 0;
}

// ---------------- K4: per-item bisection precomputes ----------------
__global__ void k_coef(void) {
    int n = blockIdx.x * blockDim.x + threadIdx.x;
    if (n >= NITEM) return;
    float m[8];
    #pragma unroll
    for (int j = 0; j < 8; j++) m[j] = d_mlp[n*8 + j];
    float2 h[2][2];
    #pragma unroll
    for (int k = 0; k < 2; k++)
        #pragma unroll
        for (int j = 0; j < 2; j++) h[k][j] = d_Hc[n*4 + k*2 + j];

    float2 U[2], Wm[2], UW[2], coef[2];
    #pragma unroll
    for (int k = 0; k < 2; k++) {
        U[k]  = make_float2(m[k],     m[2 + k]);
        Wm[k] = make_float2(m[4 + k], m[6 + k]);
        float au2 = U[k].x*U[k].x + U[k].y*U[k].y;
        coef[k] = make_float2(Wm[k].x*au2, Wm[k].y*au2);
        UW[k]   = cmul(U[k], Wm[k]);
    }
    float2 Bm[2][2] = {{{0,0},{0,0}},{{0,0},{0,0}}};
    #pragma unroll
    for (int k = 0; k < 2; k++)
        #pragma unroll
        for (int i = 0; i < 2; i++)
            #pragma unroll
            for (int j = 0; j < 2; j++)
                Bm[i][j] = cadd(Bm[i][j], cmul(coef[k], cmul(conj2(h[k][i]), h[k][j])));

    float2 a = Bm[0][0], bq = Bm[0][1], cq = Bm[1][0], dq = Bm[1][1];
    float2 hb[2][2];
    #pragma unroll
    for (int k = 0; k < 2; k++)
        #pragma unroll
        for (int j = 0; j < 2; j++) hb[k][j] = conj2(h[k][j]);

    float2 alpha[2][2], beta[2][2];
    #pragma unroll
    for (int k = 0; k < 2; k++) {
        float2 p0 = csub(cmul(dq, hb[k][0]), cmul(bq, hb[k][1]));
        float2 p1 = csub(cmul(a,  hb[k][1]), cmul(cq, hb[k][0]));
        alpha[0][k] = cmul(UW[k], p0);
        alpha[1][k] = cmul(UW[k], p1);
        beta[0][k]  = cmul(UW[k], hb[k][0]);
        beta[1][k]  = cmul(UW[k], hb[k][1]);
    }
    float2 det0 = csub(cmul(a, dq), cmul(bq, cq));
    float2 s    = cadd(a, dq);

    float A = 0.f, Bc = 0.f, Cc = 0.f;
    #pragma unroll
    for (int i = 0; i < 2; i++)
        #pragma unroll
        for (int k = 0; k < 2; k++) {
            A  += alpha[i][k].x*alpha[i][k].x + alpha[i][k].y*alpha[i][k].y;
            Bc += alpha[i][k].x*beta[i][k].x  + alpha[i][k].y*beta[i][k].y;
            Cc += beta[i][k].x*beta[i][k].x   + beta[i][k].y*beta[i][k].y;
        }
    Bc *= 4.f; Cc *= 4.f;

    float* pp = &d_poly[n*8];
    pp[0]=A; pp[1]=Bc; pp[2]=Cc; pp[3]=det0.x; pp[4]=det0.y; pp[5]=s.x; pp[6]=s.y; pp[7]=0.f;
    float* vp = &d_vp[n*16];
    #pragma unroll
    for (int i = 0; i < 2; i++)
        #pragma unroll
        for (int k = 0; k < 2; k++) {
            int e = i*2 + k;
            vp[e*2]     = alpha[i][k].x;  vp[e*2 + 1]     = alpha[i][k].y;
            vp[8 + e*2] = beta[i][k].x;   vp[8 + e*2 + 1] = beta[i][k].y;
        }
}

// ---------------- K5: 5 bisection levels per launch ----------------
__global__ __launch_bounds__(BBLK) void k_bisect5(void) {
    float lo = d_state[0], hi = d_state[1];
    float L[32], Hh[32], MU[32];
    L[1] = lo; Hh[1] = hi;
    #pragma unroll
    for (int nn = 1; nn < 32; nn++) {
        MU[nn] = (L[nn] + Hh[nn]) * 0.5f;
        if (nn < 16) {
            L[2*nn] = L[nn];  Hh[2*nn] = MU[nn];
            L[2*nn+1] = MU[nn]; Hh[2*nn+1] = Hh[nn];
        }
    }
    int n = blockIdx.x * BBLK + threadIdx.x;
    const float* pp = &d_poly[n*8];
    float A = pp[0], Bc = pp[1], Cc = pp[2], d0r = pp[3], d0i = pp[4], sr = pp[5], si = pp[6];
    float val[31];
    #pragma unroll
    for (int j = 0; j < 31; j++) {
        float mu = MU[j + 1];
        float dr = d0r + 2.f*mu*sr + 4.f*mu*mu;
        float di = d0i + 2.f*mu*si;
        val[j] = (A + Bc*mu + Cc*mu*mu) / (dr*dr + di*di);
    }
    #pragma unroll
    for (int j = 0; j < 31; j++)
        #pragma unroll
        for (int o = 16; o; o >>= 1) val[j] += __shfl_down_sync(0xffffffffu, val[j], o);

    __shared__ float sm[8*31];
    int w = threadIdx.x >> 5, lane = threadIdx.x & 31;
    if (lane == 0) {
        #pragma unroll
        for (int j = 0; j < 31; j++) sm[w*31 + j] = val[j];
    }
    __syncthreads();
    if (threadIdx.x < 31) {
        float s = 0.f;
        #pragma unroll
        for (int w2 = 0; w2 < 8; w2++) s += sm[w2*31 + threadIdx.x];
        d_part5[blockIdx.x*31 + threadIdx.x] = s;
    }
    __threadfence();
    __shared__ int isLast;
    if (threadIdx.x == 0) isLast = (atomicAdd(&d_cnt, 1) == BGRD - 1);
    __syncthreads();
    if (!isLast) return;

    if (threadIdx.x < 31) {
        float s = 0.f;
        for (int bb = 0; bb < BGRD; bb++) s += d_part5[bb*31 + threadIdx.x];
        sm[threadIdx.x] = s;
    }
    __syncthreads();
    if (threadIdx.x == 0) {
        d_cnt = 0;
        float llo = lo, lhi = hi, mu = d_state[3];
        int it = d_it[0];
        int nid = 1;
        #pragma unroll
        for (int s5 = 0; s5 < 5; s5++) {
            if (lhi - llo >= EPSB && it <= 100) {
                mu = MU[nid];
                float S = sm[nid - 1];
                if (S > P_TGT) { llo = mu; nid = 2*nid + 1; }
                else           { lhi = mu; nid = 2*nid;     }
                it++;
            }
        }
        d_state[0] = llo; d_state[1] = lhi; d_state[3] = mu;
        d_it[0] = it;
    }
}

// ---------------- K6: final V + Power (fused) ----------------
__global__ void k_powv(void) {
    int warp = (blockIdx.x * blockDim.x + threadIdx.x) >> 5;
    int lane = threadIdx.x & 31;
    if (warp >= NITEM) return;
    int n = warp;
    int b = n >> 5, c = n & 31;
    int bp = ((b & 127) << 5) + c;
    float mu = d_state[3];
    const float* pp = &d_poly[n*8];
    float dr = pp[3] + 2.f*mu*pp[5] + 4.f*mu*mu;
    float di = pp[4] + 2.f*mu*pp[6];
    float den = dr*dr + di*di;
    float2 idet = make_float2(dr/den, -di/den);
    const float* vp = &d_vp[n*16];
    float2 v[2][2];
    #pragma unroll
    for (int i = 0; i < 2; i++)
        #pragma unroll
        for (int k = 0; k < 2; k++) {
            int e = i*2 + k;
            float2 al = make_float2(vp[e*2],     vp[e*2 + 1]);
            float2 be = make_float2(vp[8 + e*2], vp[8 + e*2 + 1]);
            float2 num = make_float2(al.x + 2.f*mu*be.x, al.y + 2.f*mu*be.y);
            v[i][k] = cmul(num, idet);
        }
    float acc = 0.f;
    #pragma unroll
    for (int tt = 0; tt < 2; tt++) {
        int t = lane + tt*32;
        float4 f = d_FRF[bp*64 + t];
        #pragma unroll
        for (int k = 0; k < 2; k++) {
            float orr = f.x*v[0][k].x - f.y*v[0][k].y + f.z*v[1][k].x - f.w*v[1][k].y;
            float oii = f.x*v[0][k].y + f.y*v[0][k].x + f.z*v[1][k].y + f.w*v[1][k].x;
            acc += orr*orr + oii*oii;
        }
    }
    acc = wred(acc);
    if (lane == 0) {
        d_P[n] = acc;
        #pragma unroll
        for (int e = 0; e < 4; e++) d_V[n*4 + e] = v[e >> 1][e & 1];
    }
}

// ---------------- K7: final output ----------------
__global__ void k_out(float* __restrict__ out) {
    int warp = (blockIdx.x * blockDim.x + threadIdx.x) >> 5;
    int lane = threadIdx.x & 31;
    if (warp >= NITEM) return;
    int n = warp;
    int b = n >> 5, c = n & 31;
    int bv = c*128 + (b >> 5);
    int cv = b & 31;
    int nv = bv*32 + cv;
    float Pw = d_P[n];
    float sc = sqrtf(2.0f) / sqrtf(Pw);
    float2 v[2][2];
    #pragma unroll
    for (int i = 0; i < 2; i++)
        #pragma unroll
        for (int k = 0; k < 2; k++) {
            float2 t2 = d_V[nv*4 + i*2 + k];
            v[i][k] = make_float2(t2.x*sc, t2.y*sc);
        }
    float* outre = out + (size_t)b*8192 + c*128;
    float* outim = outre + 4096;
    #pragma unroll
    for (int tt = 0; tt < 2; tt++) {
        int t = lane + tt*32;
        float4 f = d_FRF[b*64 + t];
        float o0r = f.x*v[0][0].x - f.y*v[0][0].y + f.z*v[1][0].x - f.w*v[1][0].y;
        float o0i = f.x*v[0][0].y + f.y*v[0][0].x + f.z*v[1][0].y + f.w*v[1][0].x;
        float o1r = f.x*v[0][1].x - f.y*v[0][1].y + f.z*v[1][1].x - f.w*v[1][1].y;
        float o1i = f.x*v[0][1].y + f.y*v[0][1].x + f.z*v[1][1].y + f.w*v[1][1].x;
        ((float2*)outre)[t] = make_float2(o0r, o1r);
        ((float2*)outim)[t] = make_float2(o0i, o1i);
    }
}

// ---------------- launch ----------------
extern "C" void kernel_launch(void* const* d_in, const int* in_sizes, int n_in,
                              void* d_out, int out_size) {
    (void)in_sizes; (void)n_in; (void)out_size;
    const float* H  = (const float*)d_in[0];
    const float* W0 = (const float*)d_in[1];
    const float* b0 = (const float*)d_in[2];
    const float* W1 = (const float*)d_in[3];
    const float* b1 = (const float*)d_in[4];
    const float* W2 = (const float*)d_in[5];
    const float* b2 = (const float*)d_in[6];
    const float* W3 = (const float*)d_in[7];
    const float* b3 = (const float*)d_in[8];
    float* out = (float*)d_out;

    cudaFuncSetAttribute(k_mlp, cudaFuncAttributeMaxDynamicSharedMemorySize, MLP_SMEM);

    k_wpackh<<<128, 256>>>(W1, W2);                              // #1
    k_frf   <<<BATCHN*32/256, 256>>>(H);                         // #2
    k_hequ  <<<NITEM*32/256, 256>>>(H);                          // #3
    k_mlp   <<<NITEM/MLP_R, 512, MLP_SMEM>>>(W0, b0, b1, b2, W3, b3);  // #4 -> ncu slot
    k_init  <<<1, 1>>>();                                        // #5
    k_coef  <<<NITEM/256, 256>>>();                              // #6
    for (int it = 0; it < 4; it++)
        k_bisect5<<<BGRD, BBLK>>>();
    k_powv  <<<NITEM*32/256, 256>>>();
    k_out   <<<NITEM*32/256, 256>>>(out);
}

// round 12
// speedup vs baseline: 1.1504x; 1.1504x over previous
#include <cuda_runtime.h>
#include <cuda_fp16.h>
#include <math.h>

// ---------------- problem constants ----------------
#define NC     32
#define NT     64
#define BATCHN 4096
#define NITEM  (BATCHN*NC)      // 131072 (b,c) items
#define P_TGT  1.0f
#define EPSB   1e-5f

// ---------------- MLP config ----------------
#define MLP_R   64                  // rows per CTA
#define AST     264                 // half-stride per activation row (528B, 16B-rotating)
#define SM_AL_OFF 16896             // AL base (half index) = 64*264
#define SM_XS_OFF 67584             // byte offset of staged inputs
#define MLP_SMEM (67584 + 2048)     // 69632 bytes

// bisection config
#define BGRD 512
#define BBLK 256

// ---------------- scratch (device globals; no allocation) ----------------
__device__ float4 d_FRF[BATCHN*NT];
__device__ float2 d_Hc [NITEM*4];
__device__ float  d_x  [NITEM*8];
__device__ float  d_mlp[NITEM*8];
__device__ float  d_poly[NITEM*8];
__device__ float  d_vp [NITEM*16];
__device__ float2 d_V  [NITEM*4];
__device__ float  d_P  [NITEM];
__device__ uint4  d_Wbp[32768];     // [L][s][n][kq] = {bh0,bh1,bl0,bl1}  512KB
__device__ float  d_part5[BGRD*31];
__device__ float  d_state[4];
__device__ int    d_it[1];
__device__ int    d_cnt;

// ---------------- helpers ----------------
__device__ __forceinline__ float2 cmul(float2 a, float2 b) {
    return make_float2(a.x*b.x - a.y*b.y, a.x*b.y + a.y*b.x);
}
__device__ __forceinline__ float2 cadd(float2 a, float2 b){ return make_float2(a.x+b.x, a.y+b.y); }
__device__ __forceinline__ float2 csub(float2 a, float2 b){ return make_float2(a.x-b.x, a.y-b.y); }
__device__ __forceinline__ float2 conj2(float2 a){ return make_float2(a.x, -a.y); }
__device__ __forceinline__ float wred(float v){
    #pragma unroll
    for (int o = 16; o; o >>= 1) v += __shfl_down_sync(0xffffffffu, v, o);
    return v;
}
__device__ __forceinline__ unsigned smem_u32(const void* p){
    unsigned a;
    asm("{ .reg .u64 t; cvta.to.shared.u64 t, %1; cvt.u32.u64 %0, t; }" : "=r"(a) : "l"(p));
    return a;
}
__device__ __forceinline__ unsigned pkh2(float lo, float hi){
    __half2 h = __floats2half2_rn(lo, hi);
    return *(unsigned*)&h;
}
__device__ __forceinline__ void ldm4(unsigned* r, unsigned addr){
    asm volatile("ldmatrix.sync.aligned.m8n8.x4.shared.b16 {%0,%1,%2,%3}, [%4];"
        : "=r"(r[0]), "=r"(r[1]), "=r"(r[2]), "=r"(r[3]) : "r"(addr));
}
__device__ __forceinline__ void mma16816(float* d, const unsigned* a, unsigned b0, unsigned b1){
    asm volatile("mma.sync.aligned.m16n8k16.row.col.f32.f16.f16.f32 "
        "{%0,%1,%2,%3}, {%4,%5,%6,%7}, {%8,%9}, {%0,%1,%2,%3};"
        : "+f"(d[0]), "+f"(d[1]), "+f"(d[2]), "+f"(d[3])
        : "r"(a[0]), "r"(a[1]), "r"(a[2]), "r"(a[3]), "r"(b0), "r"(b1));
}

// ---------------- K1: fused weight pack + F_RF ----------------
// blocks [0,128): fp16-split weight pack; blocks [128,640): F_RF
__global__ void k_prep(const float* __restrict__ H,
                       const float* __restrict__ W1, const float* __restrict__ W2) {
    if (blockIdx.x < 128) {
        int idx = blockIdx.x * 256 + threadIdx.x;   // 32768
        int kq = idx & 3, n = (idx >> 2) & 255, s = (idx >> 10) & 15, L = idx >> 14;
        const float* W = L ? W2 : W1;
        int k0 = s*16 + kq*2;
        float v[4];
        v[0] = W[(k0    )*256 + n];
        v[1] = W[(k0 + 1)*256 + n];
        v[2] = W[(k0 + 8)*256 + n];
        v[3] = W[(k0 + 9)*256 + n];
        float h[4], l[4];
        #pragma unroll
        for (int i = 0; i < 4; i++) {
            h[i] = __half2float(__float2half_rn(v[i]));
            l[i] = v[i] - h[i];
        }
        uint4 o;
        o.x = pkh2(h[0], h[1]);
        o.y = pkh2(h[2], h[3]);
        o.z = pkh2(l[0], l[1]);
        o.w = pkh2(l[2], l[3]);
        d_Wbp[idx] = o;
    } else {
        int warp = ((blockIdx.x - 128) * 256 + threadIdx.x) >> 5;
        int lane = threadIdx.x & 31;
        if (warp >= BATCHN) return;
        int b = warp;
        const float* r0 = H + ((b*2 + 0)*32 + 16)*128;
        const float* r1 = H + ((b*2 + 1)*32 + 16)*128;
        float im0 = r0[0];
        float im1 = r1[0];
        #pragma unroll
        for (int tt = 0; tt < 2; tt++) {
            int t = lane + tt*32;
            float re0 = r0[t], re1 = r1[t];
            float m0 = sqrtf(re0*re0 + im0*im0) * 8.0f;
            float m1 = sqrtf(re1*re1 + im1*im1) * 8.0f;
            float4 f;
            f.x =  re0 / m0;  f.y = -im0 / m0;
            f.z =  re1 / m1;  f.w = -im1 / m1;
            d_FRF[b*64 + t] = f;
        }
    }
}

// ---------------- K2: H_equ (normalized) + features ----------------
__global__ void k_hequ(const float* __restrict__ H) {
    int warp = (blockIdx.x * blockDim.x + threadIdx.x) >> 5;
    int lane = threadIdx.x & 31;
    if (warp >= NITEM) return;
    int n = warp;
    int b = n >> 5, c = n & 31;
    int c3 = b >> 7;
    int b3 = ((b & 127) << 5) + c;

    float accr[2][2] = {{0,0},{0,0}};
    float acci[2][2] = {{0,0},{0,0}};
    #pragma unroll
    for (int i = 0; i < 2; i++) {
        int M  = c3*8192 + b3*2 + i;
        int bb = M >> 6, kk = (M >> 5) & 1, cc = M & 31;
        const float* row = H + ((bb*2 + kk)*32 + cc)*128;
        float him = row[0];
        #pragma unroll
        for (int tt = 0; tt < 2; tt++) {
            int t = lane + tt*32;
            float hre = row[t];
            float4 f = d_FRF[b3*64 + t];
            accr[i][0] += hre*f.x - him*f.y;
            acci[i][0] += hre*f.y + him*f.x;
            accr[i][1] += hre*f.z - him*f.w;
            acci[i][1] += hre*f.w + him*f.z;
        }
    }
    #pragma unroll
    for (int i = 0; i < 2; i++)
        #pragma unroll
        for (int k = 0; k < 2; k++) {
            accr[i][k] = wred(accr[i][k]);
            acci[i][k] = wred(acci[i][k]);
        }
    if (lane == 0) {
        float pw = 0.f;
        #pragma unroll
        for (int i = 0; i < 2; i++)
            #pragma unroll
            for (int k = 0; k < 2; k++)
                pw += accr[i][k]*accr[i][k] + acci[i][k]*acci[i][k];
        float inv = 1.0f / sqrtf(pw);
        #pragma unroll
        for (int i = 0; i < 2; i++)
            #pragma unroll
            for (int k = 0; k < 2; k++) {
                float re = accr[i][k]*inv, im = acci[i][k]*inv;
                d_Hc[n*4 + i*2 + k] = make_float2(re, im);
                d_x[n*8 + i*2 + k]     = re;
                d_x[n*8 + 4 + i*2 + k] = im;
            }
    }
}

// ---------------- K3: fused MLP, fp16-split m16n8k16 + ldmatrix + B prefetch ----------------
__global__ __launch_bounds__(256, 2)
void k_mlp(const float* __restrict__ W0, const float* __restrict__ b0,
           const float* __restrict__ b1, const float* __restrict__ b2,
           const float* __restrict__ W3, const float* __restrict__ b3) {
    extern __shared__ char smem[];
    __half* AH = (__half*)smem;
    __half* AL = AH + SM_AL_OFF;
    float*  XS = (float*)(smem + SM_XS_OFF);
    unsigned sbase = smem_u32(smem);
    int t = threadIdx.x;
    int w = t >> 5, lane = t & 31;
    int row0 = blockIdx.x * MLP_R;

    for (int i = t; i < MLP_R*8; i += 256) XS[i] = d_x[row0*8 + i];
    __syncthreads();

    // L0: 8 -> 256, thread t owns column t
    {
        int c = t;
        float wv[8];
        #pragma unroll
        for (int i = 0; i < 8; i++) wv[i] = W0[i*256 + c];
        float bs = __ldg(b0 + c);
        #pragma unroll 4
        for (int r = 0; r < MLP_R; r++) {
            float acc = bs;
            #pragma unroll
            for (int i = 0; i < 8; i++) acc += XS[r*8 + i]*wv[i];
            acc = fmaxf(acc, 0.f);
            __half hh = __float2half_rn(acc);
            AH[r*AST + c] = hh;
            AL[r*AST + c] = __float2half_rn(acc - __half2float(hh));
        }
    }
    __syncthreads();

    for (int L = 0; L < 2; L++) {
        float acc[4][4][4];
        #pragma unroll
        for (int mt = 0; mt < 4; mt++)
            #pragma unroll
            for (int nt = 0; nt < 4; nt++)
                #pragma unroll
                for (int e = 0; e < 4; e++) acc[mt][nt][e] = 0.f;

        const uint4* WB = d_Wbp + (unsigned)(L*16)*1024;
        unsigned nbq = (unsigned)(w*32 + (lane >> 2))*4 + (lane & 3);
        // ldmatrix base address for this thread (rows of the m16 tile)
        unsigned abase = sbase + (unsigned)(lane & 15)*528 + ((unsigned)(lane >> 4) & 1)*16;

        // prefetch B for s=0
        uint4 bv[4];
        #pragma unroll
        for (int nt = 0; nt < 4; nt++) bv[nt] = WB[nbq + (unsigned)(nt*8)*4];

        #pragma unroll 2
        for (int s = 0; s < 16; s++) {
            // prefetch B for s+1 (wraps at the tail; value unused there)
            uint4 bvn[4];
            unsigned sn = (unsigned)((s + 1) & 15)*1024;
            #pragma unroll
            for (int nt = 0; nt < 4; nt++) bvn[nt] = WB[sn + nbq + (unsigned)(nt*8)*4];

            #pragma unroll
            for (int mt = 0; mt < 4; mt++) {
                unsigned ah[4], al[4];
                unsigned ad = abase + (unsigned)(mt*16)*528 + (unsigned)s*32;
                ldm4(ah, ad);
                ldm4(al, ad + 33792);
                #pragma unroll
                for (int nt = 0; nt < 4; nt++) {
                    mma16816(acc[mt][nt], ah, bv[nt].x, bv[nt].y);
                    mma16816(acc[mt][nt], ah, bv[nt].z, bv[nt].w);
                    mma16816(acc[mt][nt], al, bv[nt].x, bv[nt].y);
                }
            }
            #pragma unroll
            for (int nt = 0; nt < 4; nt++) bv[nt] = bvn[nt];
        }
        __syncthreads();   // all reads of AH/AL complete

        if (L == 0) {
            // bias + relu + fp16 split -> back into AH/AL
            #pragma unroll
            for (int mt = 0; mt < 4; mt++)
                #pragma unroll
                for (int nt = 0; nt < 4; nt++) {
                    int r0 = mt*16 + (lane >> 2);
                    int c0 = w*32 + nt*8 + 2*(lane & 3);
                    #pragma unroll
                    for (int e = 0; e < 4; e++) {
                        int r = r0 + (e >> 1)*8;
                        int c = c0 + (e & 1);
                        float x = fmaxf(acc[mt][nt][e] + __ldg(b1 + c), 0.f);
                        __half hh = __float2half_rn(x);
                        AH[r*AST + c] = hh;
                        AL[r*AST + c] = __float2half_rn(x - __half2float(hh));
                    }
                }
            __syncthreads();
        } else {
            // bias + relu -> float acts in smem (reuse AH/AL region), then L3
            float* AF = (float*)smem;   // stride 264 floats per row
            #pragma unroll
            for (int mt = 0; mt < 4; mt++)
                #pragma unroll
                for (int nt = 0; nt < 4; nt++) {
                    int r0 = mt*16 + (lane >> 2);
                    int c0 = w*32 + nt*8 + 2*(lane & 3);
                    #pragma unroll
                    for (int e = 0; e < 4; e++) {
                        int r = r0 + (e >> 1)*8;
                        int c = c0 + (e & 1);
                        AF[r*264 + c] = fmaxf(acc[mt][nt][e] + __ldg(b2 + c), 0.f);
                    }
                }
            __syncthreads();

            int r = t >> 2, p2 = t & 3;
            float a0 = __ldg(b3 + 2*p2), a1 = __ldg(b3 + 2*p2 + 1);
            const float* rowf = AF + r*264;
            #pragma unroll 4
            for (int c = 0; c < 256; c++) {
                float v = rowf[c];
                a0 += v * __ldg(W3 + c*8 + 2*p2);
                a1 += v * __ldg(W3 + c*8 + 2*p2 + 1);
            }
            d_mlp[(row0 + r)*8 + 2*p2]     = a0;
            d_mlp[(row0 + r)*8 + 2*p2 + 1] = a1;
        }
    }
}

// ---------------- K0: bisection state init ----------------
__global__ void k_init(void) {
    d_state[0] = 0.0f; d_state[1] = 10.0f; d_state[2] = 0.0f; d_state[3] = 5.0f;
    d_it[0] = 0; d_cnt = 0;
}

// ---------------- K4: per-item bisection precomputes (vectorized I/O) ----------------
__global__ void k_coef(void) {
    int n = blockIdx.x * blockDim.x + threadIdx.x;
    if (n >= NITEM) return;
    float4 m0 = ((const float4*)d_mlp)[n*2];
    float4 m1 = ((const float4*)d_mlp)[n*2 + 1];
    float m[8] = {m0.x, m0.y, m0.z, m0.w, m1.x, m1.y, m1.z, m1.w};
    float4 h0 = ((const float4*)d_Hc)[n*2];
    float4 h1 = ((const float4*)d_Hc)[n*2 + 1];
    float2 h[2][2];
    h[0][0] = make_float2(h0.x, h0.y); h[0][1] = make_float2(h0.z, h0.w);
    h[1][0] = make_float2(h1.x, h1.y); h[1][1] = make_float2(h1.z, h1.w);

    float2 U[2], Wm[2], UW[2], coef[2];
    #pragma unroll
    for (int k = 0; k < 2; k++) {
        U[k]  = make_float2(m[k],     m[2 + k]);
        Wm[k] = make_float2(m[4 + k], m[6 + k]);
        float au2 = U[k].x*U[k].x + U[k].y*U[k].y;
        coef[k] = make_float2(Wm[k].x*au2, Wm[k].y*au2);
        UW[k]   = cmul(U[k], Wm[k]);
    }
    float2 Bm[2][2] = {{{0,0},{0,0}},{{0,0},{0,0}}};
    #pragma unroll
    for (int k = 0; k < 2; k++)
        #pragma unroll
        for (int i = 0; i < 2; i++)
            #pragma unroll
            for (int j = 0; j < 2; j++)
                Bm[i][j] = cadd(Bm[i][j], cmul(coef[k], cmul(conj2(h[k][i]), h[k][j])));

    float2 a = Bm[0][0], bq = Bm[0][1], cq = Bm[1][0], dq = Bm[1][1];
    float2 hb[2][2];
    #pragma unroll
    for (int k = 0; k < 2; k++)
        #pragma unroll
        for (int j = 0; j < 2; j++) hb[k][j] = conj2(h[k][j]);

    float2 alpha[2][2], beta[2][2];
    #pragma unroll
    for (int k = 0; k < 2; k++) {
        float2 p0 = csub(cmul(dq, hb[k][0]), cmul(bq, hb[k][1]));
        float2 p1 = csub(cmul(a,  hb[k][1]), cmul(cq, hb[k][0]));
        alpha[0][k] = cmul(UW[k], p0);
        alpha[1][k] = cmul(UW[k], p1);
        beta[0][k]  = cmul(UW[k], hb[k][0]);
        beta[1][k]  = cmul(UW[k], hb[k][1]);
    }
    float2 det0 = csub(cmul(a, dq), cmul(bq, cq));
    float2 s    = cadd(a, dq);

    float A = 0.f, Bc = 0.f, Cc = 0.f;
    #pragma unroll
    for (int i = 0; i < 2; i++)
        #pragma unroll
        for (int k = 0; k < 2; k++) {
            A  += alpha[i][k].x*alpha[i][k].x + alpha[i][k].y*alpha[i][k].y;
            Bc += alpha[i][k].x*beta[i][k].x  + alpha[i][k].y*beta[i][k].y;
            Cc += beta[i][k].x*beta[i][k].x   + beta[i][k].y*beta[i][k].y;
        }
    Bc *= 4.f; Cc *= 4.f;

    ((float4*)d_poly)[n*2]     = make_float4(A, Bc, Cc, det0.x);
    ((float4*)d_poly)[n*2 + 1] = make_float4(det0.y, s.x, s.y, 0.f);
    float4* vp4 = (float4*)&d_vp[n*16];
    vp4[0] = make_float4(alpha[0][0].x, alpha[0][0].y, alpha[0][1].x, alpha[0][1].y);
    vp4[1] = make_float4(alpha[1][0].x, alpha[1][0].y, alpha[1][1].x, alpha[1][1].y);
    vp4[2] = make_float4(beta[0][0].x,  beta[0][0].y,  beta[0][1].x,  beta[0][1].y);
    vp4[3] = make_float4(beta[1][0].x,  beta[1][0].y,  beta[1][1].x,  beta[1][1].y);
}

// ---------------- K5: 5 bisection levels per launch ----------------
__global__ __launch_bounds__(BBLK) void k_bisect5(void) {
    float lo = d_state[0], hi = d_state[1];
    float L[32], Hh[32], MU[32];
    L[1] = lo; Hh[1] = hi;
    #pragma unroll
    for (int nn = 1; nn < 32; nn++) {
        MU[nn] = (L[nn] + Hh[nn]) * 0.5f;
        if (nn < 16) {
            L[2*nn] = L[nn];  Hh[2*nn] = MU[nn];
            L[2*nn+1] = MU[nn]; Hh[2*nn+1] = Hh[nn];
        }
    }
    int n = blockIdx.x * BBLK + threadIdx.x;
    const float* pp = &d_poly[n*8];
    float A = pp[0], Bc = pp[1], Cc = pp[2], d0r = pp[3], d0i = pp[4], sr = pp[5], si = pp[6];
    float val[31];
    #pragma unroll
    for (int j = 0; j < 31; j++) {
        float mu = MU[j + 1];
        float dr = d0r + 2.f*mu*sr + 4.f*mu*mu;
        float di = d0i + 2.f*mu*si;
        val[j] = (A + Bc*mu + Cc*mu*mu) / (dr*dr + di*di);
    }
    #pragma unroll
    for (int j = 0; j < 31; j++)
        #pragma unroll
        for (int o = 16; o; o >>= 1) val[j] += __shfl_down_sync(0xffffffffu, val[j], o);

    __shared__ float sm[8*31];
    int w = threadIdx.x >> 5, lane = threadIdx.x & 31;
    if (lane == 0) {
        #pragma unroll
        for (int j = 0; j < 31; j++) sm[w*31 + j] = val[j];
    }
    __syncthreads();
    if (threadIdx.x < 31) {
        float s = 0.f;
        #pragma unroll
        for (int w2 = 0; w2 < 8; w2++) s += sm[w2*31 + threadIdx.x];
        d_part5[blockIdx.x*31 + threadIdx.x] = s;
    }
    __threadfence();
    __shared__ int isLast;
    if (threadIdx.x == 0) isLast = (atomicAdd(&d_cnt, 1) == BGRD - 1);
    __syncthreads();
    if (!isLast) return;

    // last block: PARALLEL global reduction over 512 blocks x 31 candidates.
    // 8 groups x 31 cols: thread (g, c) sums rows g, g+8, ... (64 loads, 8-way parallel)
    __syncthreads();   // sm reuse safe: prior contents consumed
    {
        int c = threadIdx.x & 31, g = threadIdx.x >> 5;
        if (c < 31) {
            float s = 0.f;
            #pragma unroll 8
            for (int bb = g; bb < BGRD; bb += 8) s += d_part5[bb*31 + c];
            sm[g*31 + c] = s;
        }
    }
    __syncthreads();
    __shared__ float smf[31];
    if (threadIdx.x < 31) {
        float s = 0.f;
        #pragma unroll
        for (int g = 0; g < 8; g++) s += sm[g*31 + threadIdx.x];
        smf[threadIdx.x] = s;
    }
    __syncthreads();
    if (threadIdx.x == 0) {
        d_cnt = 0;
        float llo = lo, lhi = hi, mu = d_state[3];
        int it = d_it[0];
        int nid = 1;
        #pragma unroll
        for (int s5 = 0; s5 < 5; s5++) {
            if (lhi - llo >= EPSB && it <= 100) {
                mu = MU[nid];
                float S = smf[nid - 1];
                if (S > P_TGT) { llo = mu; nid = 2*nid + 1; }
                else           { lhi = mu; nid = 2*nid;     }
                it++;
            }
        }
        d_state[0] = llo; d_state[1] = lhi; d_state[3] = mu;
        d_it[0] = it;
    }
}

// ---------------- K6: final V + Power (fused) ----------------
__global__ void k_powv(void) {
    int warp = (blockIdx.x * blockDim.x + threadIdx.x) >> 5;
    int lane = threadIdx.x & 31;
    if (warp >= NITEM) return;
    int n = warp;
    int b = n >> 5, c = n & 31;
    int bp = ((b & 127) << 5) + c;
    float mu = d_state[3];
    const float* pp = &d_poly[n*8];
    float dr = pp[3] + 2.f*mu*pp[5] + 4.f*mu*mu;
    float di = pp[4] + 2.f*mu*pp[6];
    float den = dr*dr + di*di;
    float2 idet = make_float2(dr/den, -di/den);
    const float* vp = &d_vp[n*16];
    float2 v[2][2];
    #pragma unroll
    for (int i = 0; i < 2; i++)
        #pragma unroll
        for (int k = 0; k < 2; k++) {
            int e = i*2 + k;
            float2 al = make_float2(vp[e*2],     vp[e*2 + 1]);
            float2 be = make_float2(vp[8 + e*2], vp[8 + e*2 + 1]);
            float2 num = make_float2(al.x + 2.f*mu*be.x, al.y + 2.f*mu*be.y);
            v[i][k] = cmul(num, idet);
        }
    float acc = 0.f;
    #pragma unroll
    for (int tt = 0; tt < 2; tt++) {
        int t = lane + tt*32;
        float4 f = d_FRF[bp*64 + t];
        #pragma unroll
        for (int k = 0; k < 2; k++) {
            float orr = f.x*v[0][k].x - f.y*v[0][k].y + f.z*v[1][k].x - f.w*v[1][k].y;
            float oii = f.x*v[0][k].y + f.y*v[0][k].x + f.z*v[1][k].y + f.w*v[1][k].x;
            acc += orr*orr + oii*oii;
        }
    }
    acc = wred(acc);
    if (lane == 0) {
        d_P[n] = acc;
        #pragma unroll
        for (int e = 0; e < 4; e++) d_V[n*4 + e] = v[e >> 1][e & 1];
    }
}

// ---------------- K7: final output ----------------
__global__ void k_out(float* __restrict__ out) {
    int warp = (blockIdx.x * blockDim.x + threadIdx.x) >> 5;
    int lane = threadIdx.x & 31;
    if (warp >= NITEM) return;
    int n = warp;
    int b = n >> 5, c = n & 31;
    int bv = c*128 + (b >> 5);
    int cv = b & 31;
    int nv = bv*32 + cv;
    float Pw = d_P[n];
    float sc = sqrtf(2.0f) / sqrtf(Pw);
    float2 v[2][2];
    #pragma unroll
    for (int i = 0; i < 2; i++)
        #pragma unroll
        for (int k = 0; k < 2; k++) {
            float2 t2 = d_V[nv*4 + i*2 + k];
            v[i][k] = make_float2(t2.x*sc, t2.y*sc);
        }
    float* outre = out + (size_t)b*8192 + c*128;
    float* outim = outre + 4096;
    #pragma unroll
    for (int tt = 0; tt < 2; tt++) {
        int t = lane + tt*32;
        float4 f = d_FRF[b*64 + t];
        float o0r = f.x*v[0][0].x - f.y*v[0][0].y + f.z*v[1][0].x - f.w*v[1][0].y;
        float o0i = f.x*v[0][0].y + f.y*v[0][0].x + f.z*v[1][0].y + f.w*v[1][0].x;
        float o1r = f.x*v[0][1].x - f.y*v[0][1].y + f.z*v[1][1].x - f.w*v[1][1].y;
        float o1i = f.x*v[0][1].y + f.y*v[0][1].x + f.z*v[1][1].y + f.w*v[1][1].x;
        ((float2*)outre)[t] = make_float2(o0r, o1r);
        ((float2*)outim)[t] = make_float2(o0i, o1i);
    }
}

// ---------------- launch ----------------
extern "C" void kernel_launch(void* const* d_in, const int* in_sizes, int n_in,
                              void* d_out, int out_size) {
    (void)in_sizes; (void)n_in; (void)out_size;
    const float* H  = (const float*)d_in[0];
    const float* W0 = (const float*)d_in[1];
    const float* b0 = (const float*)d_in[2];
    const float* W1 = (const float*)d_in[3];
    const float* b1 = (const float*)d_in[4];
    const float* W2 = (const float*)d_in[5];
    const float* b2 = (const float*)d_in[6];
    const float* W3 = (const float*)d_in[7];
    const float* b3 = (const float*)d_in[8];
    float* out = (float*)d_out;

    cudaFuncSetAttribute(k_mlp, cudaFuncAttributeMaxDynamicSharedMemorySize, MLP_SMEM);

    k_prep  <<<640, 256>>>(H, W1, W2);                           // #1
    k_hequ  <<<NITEM*32/256, 256>>>(H);                          // #2
    k_init  <<<1, 1>>>();                                        // #3
    k_mlp   <<<NITEM/MLP_R, 256, MLP_SMEM>>>(W0, b0, b1, b2, W3, b3);  // #4 -> ncu slot
    k_coef  <<<NITEM/256, 256>>>();                              // #5
    for (int it = 0; it < 4; it++)
        k_bisect5<<<BGRD, BBLK>>>();
    k_powv  <<<NITEM*32/256, 256>>>();
    k_out   <<<NITEM*32/256, 256>>>(out);
}